// round 12
// baseline (speedup 1.0000x reference)
#include <cuda_runtime.h>
#include <cuda_fp16.h>
#include <math.h>
#include <float.h>
#include <stdint.h>

#define NN   50000
#define NE   400000
#define NEF  450000    // NE + NN self loops
#define FIN  128
#define HC   256
#define NH   4
#define CD   64
#define EDIM 16
#define NGRP 64
#define NOUT 10

// ---------------- scratch (device globals; no allocation allowed) ----------
static __device__ __align__(16) float g_h[NN * HC];     // h = X @ W
static __device__ __align__(16) float g_add[NN * HC];   // residual accumulator
static __device__ float g_mea[NN * EDIM];               // mean edge_attr per dst
static __device__ int   g_degi[NN];
static __device__ float g_als[NN * NH];
static __device__ float g_ald[NN * NH];
static __device__ __align__(16) float g_alpha[(size_t)NEF * NH];
static __device__ float g_weeff3[3 * EDIM * NH];
static __device__ float g_t[NN];
static __device__ float g_score[NN];
static __device__ int   g_gstart[NGRP + 1];
static __device__ int   g_perm[NN];
// CSR by destination (built once, reused for all 3 layers)
static __device__ int   g_rowstart[NN + 1];
static __device__ int   g_cursor[NN];
static __device__ int   g_csrsrc[NE];
static __device__ int   g_csre[NE];
// pre-split weight planes (fp16 hi/lo), [k][n] row-major, 3 layers
static __device__ __align__(16) unsigned short g_wp_hi[3 * HC * HC];
static __device__ __align__(16) unsigned short g_wp_lo[3 * HC * HC];
// pre-split activation planes (fp16 hi/lo) -- GEMM A operand, [m][k]
static __device__ __align__(16) unsigned short g_ap_hi[NN * HC];
static __device__ __align__(16) unsigned short g_ap_lo[NN * HC];

// ---------------- helpers ----------------------------------------------------
__device__ __forceinline__ void split2(float v, unsigned short& hi, unsigned short& lo) {
    __half h = __float2half_rn(v);
    hi = __half_as_ushort(h);
    float r = v - __half2float(h);
    lo = __half_as_ushort(__float2half_rn(r));
}
__device__ __forceinline__ void cp16(uint32_t saddr, const void* g, int sz) {
    asm volatile("cp.async.cg.shared.global [%0], [%1], 16, %2;\n"
                 :: "r"(saddr), "l"(g), "r"(sz));
}
__device__ __forceinline__ void cp_commit() {
    asm volatile("cp.async.commit_group;\n");
}
template <int N>
__device__ __forceinline__ void cp_wait() {
    asm volatile("cp.async.wait_group %0;\n" :: "n"(N));
}

// ---------------- prologue: zero + degree+mean edge_attr (merged) -----------
__global__ void k_init0() {
    int i = blockIdx.x * blockDim.x + threadIdx.x;
    if (i < NN * EDIM) g_mea[i] = 0.f;
    if (i < NN) { g_degi[i] = 0; g_cursor[i] = 0; }
}
__global__ void k_measum(const int* __restrict__ dst, const float* __restrict__ ea) {
    int i = blockIdx.x * blockDim.x + threadIdx.x;
    if (i >= NE * EDIM) return;
    int e = i >> 4, j = i & 15;
    int d = dst[e];
    if (j == 0) atomicAdd(&g_degi[d], 1);
    atomicAdd(&g_mea[d * EDIM + j], ea[i]);
}
__global__ void k_meadiv() {
    int i = blockIdx.x * blockDim.x + threadIdx.x;
    if (i >= NN * EDIM) return;
    g_mea[i] /= fmaxf((float)g_degi[i >> 4], 1.f);
}

// ---------------- fast exclusive scan (shfl-based, 4096/chunk) --------------
__global__ void k_scan() {
    __shared__ int wsum[32];
    __shared__ int soff_s;
    int tid = threadIdx.x, lane = tid & 31, w = tid >> 5;
    if (tid == 0) soff_s = 0;
    __syncthreads();
    for (int chunk = 0; chunk < NN; chunk += 4096) {
        int idx = chunk + tid * 4;
        int v[4];
#pragma unroll
        for (int q = 0; q < 4; q++) v[q] = (idx + q < NN) ? g_degi[idx + q] : 0;
        int t = v[0] + v[1] + v[2] + v[3];
        int sc = t;
#pragma unroll
        for (int s = 1; s < 32; s <<= 1) {
            int u = __shfl_up_sync(0xFFFFFFFFu, sc, s);
            if (lane >= s) sc += u;
        }
        if (lane == 31) wsum[w] = sc;
        __syncthreads();
        if (w == 0) {
            int ws = wsum[lane];
#pragma unroll
            for (int s = 1; s < 32; s <<= 1) {
                int u = __shfl_up_sync(0xFFFFFFFFu, ws, s);
                if (lane >= s) ws += u;
            }
            wsum[lane] = ws;
        }
        __syncthreads();
        int base = soff_s + (w ? wsum[w - 1] : 0) + sc - t;
#pragma unroll
        for (int q = 0; q < 4; q++) {
            if (idx + q < NN) g_rowstart[idx + q] = base;
            base += v[q];
        }
        __syncthreads();
        if (tid == 0) soff_s += wsum[31];
        __syncthreads();
    }
    if (threadIdx.x == 0) g_rowstart[NN] = NE;
}

__global__ void k_fill(const int* __restrict__ src, const int* __restrict__ dst) {
    int e = blockIdx.x * blockDim.x + threadIdx.x;
    if (e >= NE) return;
    int d = dst[e];
    int pos = atomicAdd(&g_cursor[d], 1);
    int idx = g_rowstart[d] + pos;
    g_csrsrc[idx] = src[e];
    g_csre[idx] = e;
}

// ---------------- split ALL weight matrices upfront (fp16 hi/lo planes) -----
__global__ void k_prepw(const float* __restrict__ W1, const float* __restrict__ W2,
                        const float* __restrict__ W3) {
    int i = blockIdx.x * blockDim.x + threadIdx.x;
    const float* W; int idx; size_t off;
    if (i < FIN * HC)                      { W = W1; idx = i;                off = 0; }
    else if (i < FIN * HC + HC * HC)       { W = W2; idx = i - FIN * HC;     off = (size_t)HC * HC; }
    else if (i < FIN * HC + 2 * HC * HC)   { W = W3; idx = i - FIN * HC - HC * HC; off = (size_t)2 * HC * HC; }
    else return;
    unsigned short h, l;
    split2(W[idx], h, l);
    g_wp_hi[off + idx] = h; g_wp_lo[off + idx] = l;
}

// ---------------- per-layer: zero attention-logit accumulators --------------
__global__ void k_zals() {
    int i = blockIdx.x * blockDim.x + threadIdx.x;
    if (i < NN * NH) { g_als[i] = 0.f; g_ald[i] = 0.f; }
}

// ---------------- split layer-1 input x into fp16 planes --------------------
__global__ void k_splitx(const float* __restrict__ x) {
    int i = (blockIdx.x * blockDim.x + threadIdx.x) * 2;
    if (i >= NN * FIN) return;
    float2 v = *(const float2*)&x[i];
    unsigned short h0, l0, h1, l1;
    split2(v.x, h0, l0);
    split2(v.y, h1, l1);
    *(uint32_t*)&g_ap_hi[i] = (uint32_t)h0 | ((uint32_t)h1 << 16);
    *(uint32_t*)&g_ap_lo[i] = (uint32_t)l0 | ((uint32_t)l1 << 16);
}

// ---------------- tensor-core GEMM (fp16x3 ~= fp32), cp.async 2-stage -------
__device__ __forceinline__ void ldsm_x4(uint32_t& r0, uint32_t& r1, uint32_t& r2,
                                        uint32_t& r3, uint32_t addr) {
    asm volatile("ldmatrix.sync.aligned.m8n8.x4.shared.b16 {%0,%1,%2,%3}, [%4];"
                 : "=r"(r0), "=r"(r1), "=r"(r2), "=r"(r3) : "r"(addr));
}
__device__ __forceinline__ void ldsm_x2t(uint32_t& r0, uint32_t& r1, uint32_t addr) {
    asm volatile("ldmatrix.sync.aligned.m8n8.x2.trans.shared.b16 {%0,%1}, [%2];"
                 : "=r"(r0), "=r"(r1) : "r"(addr));
}
__device__ __forceinline__ void mma_f16(float* d, const uint32_t* a, const uint32_t* b) {
    asm volatile(
        "mma.sync.aligned.m16n8k16.row.col.f32.f16.f16.f32 "
        "{%0,%1,%2,%3}, {%4,%5,%6,%7}, {%8,%9}, {%0,%1,%2,%3};"
        : "+f"(d[0]), "+f"(d[1]), "+f"(d[2]), "+f"(d[3])
        : "r"(a[0]), "r"(a[1]), "r"(a[2]), "r"(a[3]), "r"(b[0]), "r"(b[1]));
}

#define ASTR 40
#define BSTR 136
#define A_PL (128 * ASTR)                 // shorts per A plane (5120)
#define B_PL (32 * BSTR)                  // shorts per B plane (4352)
#define STG  (2 * A_PL + 2 * B_PL)        // shorts per stage (18944)
#define SMEM_BYTES (2 * STG * 2)          // 75776 bytes

__global__ void __launch_bounds__(256, 2) k_gemm(int K,
                                                 const float* __restrict__ as_,
                                                 const float* __restrict__ ad_,
                                                 int l) {
    extern __shared__ unsigned short smem_u[];
    const unsigned short* gA[2] = {g_ap_hi, g_ap_lo};
    const unsigned short* gW[2] = {g_wp_hi + (size_t)l * HC * HC,
                                   g_wp_lo + (size_t)l * HC * HC};

    const int tid = threadIdx.x;
    const int lane = tid & 31;
    const int wid = tid >> 5;
    const int wm = (wid >> 2) * 64;
    const int wn = (wid & 3) * 32;
    const int rowBase = blockIdx.y * 128;
    const int n0 = blockIdx.x * 128;

    float acc[4][4][4];
#pragma unroll
    for (int i = 0; i < 4; i++)
#pragma unroll
        for (int j = 0; j < 4; j++)
#pragma unroll
            for (int q = 0; q < 4; q++) acc[i][j][q] = 0.f;

    const uint32_t sbase = (uint32_t)__cvta_generic_to_shared(smem_u);
    const int nk = K / 32;

    auto do_stage = [&](int k0, int s) {
        uint32_t sb = sbase + s * (STG * 2);
#pragma unroll
        for (int q = 0; q < 2; q++) {
            int c = tid * 2 + q;
            int row = c >> 2, col8 = (c & 3) * 8;
            int gm = rowBase + row;
            int sz = (gm < NN) ? 16 : 0;
            int gmc = (gm < NN) ? gm : (NN - 1);
            size_t goff = (size_t)gmc * K + k0 + col8;
            uint32_t so = sb + (row * ASTR + col8) * 2;
#pragma unroll
            for (int p = 0; p < 2; p++)
                cp16(so + p * (A_PL * 2), &gA[p][goff], sz);
        }
#pragma unroll
        for (int q = 0; q < 2; q++) {
            int c = tid * 2 + q;
            int row = c >> 4, col8 = (c & 15) * 8;
            size_t goff = (size_t)(k0 + row) * HC + n0 + col8;
            uint32_t so = sb + (2 * A_PL + row * BSTR + col8) * 2;
#pragma unroll
            for (int p = 0; p < 2; p++)
                cp16(so + p * (B_PL * 2), &gW[p][goff], 16);
        }
    };

    do_stage(0, 0);
    cp_commit();

    for (int kb = 0; kb < nk; kb++) {
        if (kb + 1 < nk) {
            do_stage((kb + 1) * 32, (kb + 1) & 1);
            cp_commit();
            cp_wait<1>();
        } else {
            cp_wait<0>();
        }
        __syncthreads();

        uint32_t sb = sbase + (kb & 1) * (STG * 2);
#pragma unroll
        for (int ks = 0; ks < 32; ks += 16) {
            uint32_t af[2][4][4], bb[4][2];
            int arow = lane & 15;
            int acol = ks + ((lane >> 4) << 3);
#pragma unroll
            for (int p = 0; p < 2; p++) {
                uint32_t pbase = sb + p * (A_PL * 2);
#pragma unroll
                for (int i = 0; i < 4; i++) {
                    uint32_t off = ((wm + i * 16 + arow) * ASTR + acol) * 2;
                    ldsm_x4(af[p][i][0], af[p][i][1], af[p][i][2], af[p][i][3], pbase + off);
                }
            }
            int brow = ks + (lane & 15);
            {
                uint32_t pbase = sb + (2 * A_PL) * 2;
#pragma unroll
                for (int j = 0; j < 4; j++) {
                    uint32_t off = (brow * BSTR + wn + j * 8) * 2;
                    ldsm_x2t(bb[j][0], bb[j][1], pbase + off);
                }
#pragma unroll
                for (int i = 0; i < 4; i++)
#pragma unroll
                    for (int j = 0; j < 4; j++) {
                        mma_f16(acc[i][j], af[0][i], bb[j]);
                        mma_f16(acc[i][j], af[1][i], bb[j]);
                    }
            }
            {
                uint32_t pbase = sb + (2 * A_PL + B_PL) * 2;
#pragma unroll
                for (int j = 0; j < 4; j++) {
                    uint32_t off = (brow * BSTR + wn + j * 8) * 2;
                    ldsm_x2t(bb[j][0], bb[j][1], pbase + off);
                }
#pragma unroll
                for (int i = 0; i < 4; i++)
#pragma unroll
                    for (int j = 0; j < 4; j++)
                        mma_f16(acc[i][j], af[0][i], bb[j]);
            }
        }
        __syncthreads();
    }

    // ---- epilogue: store h + fused attention logits (als/ald) ----
    const int head = (n0 + wn) >> 6;
    const int cbase = ((n0 + wn) & 63) + (lane & 3) * 2;
    float as8[4][2], ad8[4][2];
#pragma unroll
    for (int j = 0; j < 4; j++)
#pragma unroll
        for (int qb = 0; qb < 2; qb++) {
            int c = head * CD + cbase + j * 8 + qb;
            as8[j][qb] = as_[c];
            ad8[j][qb] = ad_[c];
        }

#pragma unroll
    for (int i = 0; i < 4; i++) {
        int r0 = rowBase + wm + i * 16 + (lane >> 2);
        float sa0 = 0.f, sd0 = 0.f, sa1 = 0.f, sd1 = 0.f;
#pragma unroll
        for (int j = 0; j < 4; j++) {
            int c = n0 + wn + j * 8 + (lane & 3) * 2;
            if (r0 < NN)
                *(float2*)&g_h[(size_t)r0 * HC + c] = make_float2(acc[i][j][0], acc[i][j][1]);
            if (r0 + 8 < NN)
                *(float2*)&g_h[(size_t)(r0 + 8) * HC + c] = make_float2(acc[i][j][2], acc[i][j][3]);
            sa0 += acc[i][j][0] * as8[j][0] + acc[i][j][1] * as8[j][1];
            sd0 += acc[i][j][0] * ad8[j][0] + acc[i][j][1] * ad8[j][1];
            sa1 += acc[i][j][2] * as8[j][0] + acc[i][j][3] * as8[j][1];
            sd1 += acc[i][j][2] * ad8[j][0] + acc[i][j][3] * ad8[j][1];
        }
#pragma unroll
        for (int s = 1; s < 4; s <<= 1) {
            sa0 += __shfl_xor_sync(0xFFFFFFFFu, sa0, s);
            sd0 += __shfl_xor_sync(0xFFFFFFFFu, sd0, s);
            sa1 += __shfl_xor_sync(0xFFFFFFFFu, sa1, s);
            sd1 += __shfl_xor_sync(0xFFFFFFFFu, sd1, s);
        }
        if ((lane & 3) == 0) {
            if (r0 < NN) {
                atomicAdd(&g_als[r0 * NH + head], sa0);
                atomicAdd(&g_ald[r0 * NH + head], sd0);
            }
            if (r0 + 8 < NN) {
                atomicAdd(&g_als[(r0 + 8) * NH + head], sa1);
                atomicAdd(&g_ald[(r0 + 8) * NH + head], sd1);
            }
        }
    }
}

// ---------------- effective edge weights (all 3 layers at once) -------------
__global__ void k_weeff3(const float* __restrict__ We1, const float* __restrict__ ae1,
                         const float* __restrict__ We2, const float* __restrict__ ae2,
                         const float* __restrict__ We3, const float* __restrict__ ae3) {
    int l = blockIdx.x;
    const float* We = (l == 0) ? We1 : (l == 1) ? We2 : We3;
    const float* ae = (l == 0) ? ae1 : (l == 1) ? ae2 : ae3;
    int tid = threadIdx.x;
    if (tid >= EDIM * NH) return;
    int d = tid >> 2, h = tid & 3;
    float s = 0.f;
    for (int c = 0; c < CD; c++) s += We[d * HC + h * CD + c] * ae[h * CD + c];
    g_weeff3[l * EDIM * NH + d * NH + h] = s;
}

// ---------------- edge logits (leaky relu'd) --------------------------------
__global__ void k_alpha(const int* __restrict__ src, const int* __restrict__ dst,
                        const float* __restrict__ ea, int l) {
    int e = blockIdx.x * blockDim.x + threadIdx.x;
    if (e >= NEF) return;
    const float* weeff = &g_weeff3[l * EDIM * NH];
    int s, d;
    const float* eap;
    if (e < NE) { s = src[e]; d = dst[e]; eap = ea + (size_t)e * EDIM; }
    else        { s = d = e - NE; eap = g_mea + (size_t)(e - NE) * EDIM; }
    float ev[16];
    *(float4*)&ev[0]  = *(const float4*)&eap[0];
    *(float4*)&ev[4]  = *(const float4*)&eap[4];
    *(float4*)&ev[8]  = *(const float4*)&eap[8];
    *(float4*)&ev[12] = *(const float4*)&eap[12];
    float ale[NH] = {0.f, 0.f, 0.f, 0.f};
#pragma unroll
    for (int dd = 0; dd < EDIM; dd++) {
        float v = ev[dd];
#pragma unroll
        for (int h = 0; h < NH; h++) ale[h] += v * weeff[dd * NH + h];
    }
    float4 out;
    float* op = (float*)&out;
#pragma unroll
    for (int h = 0; h < NH; h++) {
        float a = g_als[s * NH + h] + g_ald[d * NH + h] + ale[h];
        op[h] = (a > 0.f) ? a : 0.2f * a;
    }
    *(float4*)&g_alpha[(size_t)e * NH] = out;
}

// ---------------- gather aggregation: warp per dst, dual online softmax -----
// mode: 0 = first layer, 1 = middle, 2 = last (fused SAGPool dots, no planes)
__global__ void k_gather(const float* __restrict__ b, int mode,
                         const float* __restrict__ wrel,
                         const float* __restrict__ wroot,
                         const float* __restrict__ brel) {
    int d = blockIdx.x * (blockDim.x >> 5) + (threadIdx.x >> 5);
    int lane = threadIdx.x & 31;
    if (d >= NN) return;
    int h = lane >> 3;
    float acc0[8] = {}, acc1[8] = {};
    float m0 = -FLT_MAX, den0 = 0.f;
    float m1 = -FLT_MAX, den1 = 0.f;
    int beg = g_rowstart[d], end = g_rowstart[d + 1];
    int i = beg;
    for (; i + 1 < end; i += 2) {
        int sA = g_csrsrc[i],     eA = g_csre[i];
        int sB = g_csrsrc[i + 1], eB = g_csre[i + 1];
        float aA = g_alpha[(size_t)eA * NH + h];
        float aB = g_alpha[(size_t)eB * NH + h];
        const float4* hpA = (const float4*)&g_h[(size_t)sA * HC + lane * 8];
        const float4* hpB = (const float4*)&g_h[(size_t)sB * HC + lane * 8];
        float4 vA0 = hpA[0], vA1 = hpA[1];
        float4 vB0 = hpB[0], vB1 = hpB[1];
        {
            float mn = fmaxf(m0, aA);
            float sc = __expf(m0 - mn), ex = __expf(aA - mn);
            den0 = den0 * sc + ex;
            acc0[0] = acc0[0] * sc + ex * vA0.x; acc0[1] = acc0[1] * sc + ex * vA0.y;
            acc0[2] = acc0[2] * sc + ex * vA0.z; acc0[3] = acc0[3] * sc + ex * vA0.w;
            acc0[4] = acc0[4] * sc + ex * vA1.x; acc0[5] = acc0[5] * sc + ex * vA1.y;
            acc0[6] = acc0[6] * sc + ex * vA1.z; acc0[7] = acc0[7] * sc + ex * vA1.w;
            m0 = mn;
        }
        {
            float mn = fmaxf(m1, aB);
            float sc = __expf(m1 - mn), ex = __expf(aB - mn);
            den1 = den1 * sc + ex;
            acc1[0] = acc1[0] * sc + ex * vB0.x; acc1[1] = acc1[1] * sc + ex * vB0.y;
            acc1[2] = acc1[2] * sc + ex * vB0.z; acc1[3] = acc1[3] * sc + ex * vB0.w;
            acc1[4] = acc1[4] * sc + ex * vB1.x; acc1[5] = acc1[5] * sc + ex * vB1.y;
            acc1[6] = acc1[6] * sc + ex * vB1.z; acc1[7] = acc1[7] * sc + ex * vB1.w;
            m1 = mn;
        }
    }
    if (i < end) {
        int s = g_csrsrc[i], e = g_csre[i];
        float a = g_alpha[(size_t)e * NH + h];
        const float4* hp = (const float4*)&g_h[(size_t)s * HC + lane * 8];
        float4 v0 = hp[0], v1 = hp[1];
        float mn = fmaxf(m0, a);
        float sc = __expf(m0 - mn), ex = __expf(a - mn);
        den0 = den0 * sc + ex;
        acc0[0] = acc0[0] * sc + ex * v0.x; acc0[1] = acc0[1] * sc + ex * v0.y;
        acc0[2] = acc0[2] * sc + ex * v0.z; acc0[3] = acc0[3] * sc + ex * v0.w;
        acc0[4] = acc0[4] * sc + ex * v1.x; acc0[5] = acc0[5] * sc + ex * v1.y;
        acc0[6] = acc0[6] * sc + ex * v1.z; acc0[7] = acc0[7] * sc + ex * v1.w;
        m0 = mn;
    }
    {   // self loop (src = dst = d) into set 1
        float a = g_alpha[(size_t)(NE + d) * NH + h];
        const float4* hp = (const float4*)&g_h[(size_t)d * HC + lane * 8];
        float4 v0 = hp[0], v1 = hp[1];
        float mn = fmaxf(m1, a);
        float sc = __expf(m1 - mn), ex = __expf(a - mn);
        den1 = den1 * sc + ex;
        acc1[0] = acc1[0] * sc + ex * v0.x; acc1[1] = acc1[1] * sc + ex * v0.y;
        acc1[2] = acc1[2] * sc + ex * v0.z; acc1[3] = acc1[3] * sc + ex * v0.w;
        acc1[4] = acc1[4] * sc + ex * v1.x; acc1[5] = acc1[5] * sc + ex * v1.y;
        acc1[6] = acc1[6] * sc + ex * v1.z; acc1[7] = acc1[7] * sc + ex * v1.w;
        m1 = mn;
    }
    // merge the two softmax streams
    float m = fmaxf(m0, m1);
    float s0 = __expf(m0 - m), s1 = __expf(m1 - m);
    float den = den0 * s0 + den1 * s1;
    float inv = 1.f / (den + 1e-16f);
    int col = lane * 8;
    float o[8];
#pragma unroll
    for (int j = 0; j < 8; j++) {
        float v = (acc0[j] * s0 + acc1[j] * s1) * inv + b[col + j];
        o[j] = fmaxf(v, 0.f);
    }
    size_t base = (size_t)d * HC + col;
    if (mode != 2) {
        // split output into fp16 planes for the next GEMM
        unsigned short hs[8], ls[8];
#pragma unroll
        for (int j = 0; j < 8; j++) split2(o[j], hs[j], ls[j]);
        uint4 uh, ul;
        uh.x = (uint32_t)hs[0] | ((uint32_t)hs[1] << 16);
        uh.y = (uint32_t)hs[2] | ((uint32_t)hs[3] << 16);
        uh.z = (uint32_t)hs[4] | ((uint32_t)hs[5] << 16);
        uh.w = (uint32_t)hs[6] | ((uint32_t)hs[7] << 16);
        ul.x = (uint32_t)ls[0] | ((uint32_t)ls[1] << 16);
        ul.y = (uint32_t)ls[2] | ((uint32_t)ls[3] << 16);
        ul.z = (uint32_t)ls[4] | ((uint32_t)ls[5] << 16);
        ul.w = (uint32_t)ls[6] | ((uint32_t)ls[7] << 16);
        *(uint4*)&g_ap_hi[base] = uh;
        *(uint4*)&g_ap_lo[base] = ul;
    }
    float na[8];
    if (mode == 0) {
#pragma unroll
        for (int j = 0; j < 8; j++) na[j] = o[j];
    } else {
        float4 a0 = *(float4*)&g_add[base], a1 = *(float4*)&g_add[base + 4];
        na[0] = a0.x + o[0]; na[1] = a0.y + o[1]; na[2] = a0.z + o[2]; na[3] = a0.w + o[3];
        na[4] = a1.x + o[4]; na[5] = a1.y + o[5]; na[6] = a1.z + o[6]; na[7] = a1.w + o[7];
    }
    *(float4*)&g_add[base]     = *(float4*)&na[0];
    *(float4*)&g_add[base + 4] = *(float4*)&na[4];

    if (mode == 2) {
        // fused SAGPool row dots: t = add.wrel, score = add.wroot + brel
        float t = 0.f, r = 0.f;
#pragma unroll
        for (int j = 0; j < 8; j++) {
            t += na[j] * wrel[col + j];
            r += na[j] * wroot[col + j];
        }
#pragma unroll
        for (int s = 16; s > 0; s >>= 1) {
            t += __shfl_xor_sync(0xFFFFFFFFu, t, s);
            r += __shfl_xor_sync(0xFFFFFFFFu, r, s);
        }
        if (lane == 0) { g_t[d] = t; g_score[d] = r + brel[0]; }
    }
}

// deterministic CSR gather (double accumulate)
__global__ void k_scoreagg() {
    int d = blockIdx.x * blockDim.x + threadIdx.x;
    if (d >= NN) return;
    double s = 0.0;
    int beg = g_rowstart[d], end = g_rowstart[d + 1];
    for (int i = beg; i < end; i++) s += (double)g_t[g_csrsrc[i]];
    g_score[d] += (float)s;
}

// ---------------- group boundaries (batch is sorted) --------------------------
__global__ void k_gstart(const int* __restrict__ batch) {
    int n = blockIdx.x * blockDim.x + threadIdx.x;
    if (n >= NN) return;
    int b = batch[n];
    int prev = (n == 0) ? -1 : batch[n - 1];
    for (int g = prev + 1; g <= b; g++) g_gstart[g] = n;
    if (n == NN - 1) {
        for (int g = b + 1; g <= NGRP; g++) g_gstart[g] = NN;
    }
}

// ---------------- per-group bitonic sort (descending score, tie: asc index) --
#define SORTP 1024
__global__ void k_sort() {
    __shared__ float sk[SORTP];
    __shared__ int   sv[SORTP];
    int g = blockIdx.x;
    int start = g_gstart[g], end = g_gstart[g + 1];
    int sz = end - start;
    if (sz > SORTP) sz = SORTP;
    for (int i = threadIdx.x; i < SORTP; i += blockDim.x) {
        if (i < sz) { sk[i] = g_score[start + i]; sv[i] = start + i; }
        else        { sk[i] = -FLT_MAX; sv[i] = 0x7FFFFFFF; }
    }
    __syncthreads();
    for (int k = 2; k <= SORTP; k <<= 1) {
        for (int j = k >> 1; j > 0; j >>= 1) {
            for (int i = threadIdx.x; i < SORTP; i += blockDim.x) {
                int ixj = i ^ j;
                if (ixj > i) {
                    float ki = sk[i], kj = sk[ixj];
                    int vi = sv[i], vj = sv[ixj];
                    bool before = (kj > ki) || (kj == ki && vj < vi);
                    bool dir = ((i & k) == 0);
                    if (before == dir) {
                        sk[i] = kj; sk[ixj] = ki;
                        sv[i] = vj; sv[ixj] = vi;
                    }
                }
            }
            __syncthreads();
        }
    }
    for (int i = threadIdx.x; i < sz; i += blockDim.x) g_perm[start + i] = sv[i];
}

// ---------------- final: gate + 256->10 GEMV + sigmoid ------------------------
__global__ void k_final(const float* __restrict__ wl, const float* __restrict__ bl,
                        float* __restrict__ out) {
    __shared__ float swl[HC * NOUT];
    for (int i = threadIdx.x; i < HC * NOUT; i += blockDim.x) swl[i] = wl[i];
    __syncthreads();
    int pos = blockIdx.x * 8 + (threadIdx.x >> 5);
    int lane = threadIdx.x & 31;
    if (pos >= NN) return;
    int p = g_perm[pos];
    float ts = tanhf(g_score[p]);
    float acc[NOUT];
#pragma unroll
    for (int o = 0; o < NOUT; o++) acc[o] = 0.f;
    size_t base = (size_t)p * HC + lane * 8;
#pragma unroll
    for (int jj = 0; jj < 8; jj++) {
        float v = g_add[base + jj] * ts;
        const float* wrow = &swl[(lane * 8 + jj) * NOUT];
#pragma unroll
        for (int o = 0; o < NOUT; o++) acc[o] += v * wrow[o];
    }
#pragma unroll
    for (int s = 16; s > 0; s >>= 1)
#pragma unroll
        for (int o = 0; o < NOUT; o++) acc[o] += __shfl_xor_sync(0xFFFFFFFFu, acc[o], s);
    if (lane == 0) {
#pragma unroll
        for (int o = 0; o < NOUT; o++)
            out[(size_t)pos * NOUT + o] = 1.f / (1.f + expf(-(acc[o] + bl[o])));
    }
}

// ---------------- launch ------------------------------------------------------
extern "C" void kernel_launch(void* const* d_in, const int* in_sizes, int n_in,
                              void* d_out, int out_size) {
    const float* x     = (const float*)d_in[0];
    const int*   eidx  = (const int*)d_in[1];
    const int*   batch = (const int*)d_in[2];
    const float* ea    = (const float*)d_in[3];
    const float* W[3]  = {(const float*)d_in[4],  (const float*)d_in[10], (const float*)d_in[16]};
    const float* AS[3] = {(const float*)d_in[5],  (const float*)d_in[11], (const float*)d_in[17]};
    const float* AD[3] = {(const float*)d_in[6],  (const float*)d_in[12], (const float*)d_in[18]};
    const float* WE[3] = {(const float*)d_in[7],  (const float*)d_in[13], (const float*)d_in[19]};
    const float* AE[3] = {(const float*)d_in[8],  (const float*)d_in[14], (const float*)d_in[20]};
    const float* B[3]  = {(const float*)d_in[9],  (const float*)d_in[15], (const float*)d_in[21]};
    const float* wrel  = (const float*)d_in[22];
    const float* brel  = (const float*)d_in[23];
    const float* wroot = (const float*)d_in[24];
    const float* wl    = (const float*)d_in[25];
    const float* bl    = (const float*)d_in[26];

    const int* src = eidx;
    const int* dst = eidx + NE;

    static cudaStream_t s2 = nullptr;
    static cudaEvent_t evA = nullptr, evB = nullptr;
    static cudaEvent_t evP[2] = {nullptr, nullptr}, evQ[2] = {nullptr, nullptr};
    if (!s2) {
        cudaStreamCreateWithFlags(&s2, cudaStreamNonBlocking);
        cudaEventCreateWithFlags(&evA, cudaEventDisableTiming);
        cudaEventCreateWithFlags(&evB, cudaEventDisableTiming);
        for (int q = 0; q < 2; q++) {
            cudaEventCreateWithFlags(&evP[q], cudaEventDisableTiming);
            cudaEventCreateWithFlags(&evQ[q], cudaEventDisableTiming);
        }
        cudaFuncSetAttribute(k_gemm, cudaFuncAttributeMaxDynamicSharedMemorySize, SMEM_BYTES);
    }

    const int T = 256;

    // ---- fork: CSR/prologue chain on s2 ----
    cudaEventRecord(evA, 0);
    cudaStreamWaitEvent(s2, evA, 0);
    k_init0<<<(NN * EDIM + T - 1) / T, T, 0, s2>>>();
    k_measum<<<(NE * EDIM + T - 1) / T, T, 0, s2>>>(dst, ea);
    k_meadiv<<<(NN * EDIM + T - 1) / T, T, 0, s2>>>();
    k_scan<<<1, 1024, 0, s2>>>();
    k_fill<<<(NE + T - 1) / T, T, 0, s2>>>(src, dst);
    k_gstart<<<(NN + T - 1) / T, T, 0, s2>>>(batch);
    cudaEventRecord(evB, s2);

    // primary stream: weight/input prep + layer-0 GEMM (independent of CSR)
    k_weeff3<<<3, 64>>>(WE[0], AE[0], WE[1], AE[1], WE[2], AE[2]);
    k_splitx<<<(NN * FIN / 2 + T - 1) / T, T>>>(x);
    k_prepw<<<(FIN * HC + 2 * HC * HC + T - 1) / T, T>>>(W[0], W[1], W[2]);
    k_zals<<<(NN * NH + T - 1) / T, T>>>();

    for (int l = 0; l < 3; l++) {
        int K = (l == 0) ? FIN : HC;
        if (l > 0) cudaStreamWaitEvent(0, evQ[l - 1], 0);  // zals(l) done on s2
        k_gemm<<<dim3(HC / 128, (NN + 127) / 128), T, SMEM_BYTES>>>(K, AS[l], AD[l], l);
        if (l == 0) cudaStreamWaitEvent(0, evB, 0);  // join: alpha/gather need CSR + mea
        k_alpha<<<(NEF + T - 1) / T, T>>>(src, dst, ea, l);
        if (l < 2) {
            // overlap next layer's zals with this layer's gather (on s2)
            cudaEventRecord(evP[l], 0);
            cudaStreamWaitEvent(s2, evP[l], 0);
            k_zals<<<(NN * NH + T - 1) / T, T, 0, s2>>>();
            cudaEventRecord(evQ[l], s2);
        }
        k_gather<<<(NN + 7) / 8, T>>>(B[l], (l == 0) ? 0 : (l == 2) ? 2 : 1,
                                      wrel, wroot, brel);
    }

    // SAGPool score (deterministic CSR aggregation; t/score already computed)
    k_scoreagg<<<(NN + T - 1) / T, T>>>();

    // per-graph sort + final head
    k_sort<<<NGRP, 512>>>();
    k_final<<<(NN + 7) / 8, T>>>(wl, bl, (float*)d_out);
}

// round 13
// speedup vs baseline: 1.0302x; 1.0302x over previous
#include <cuda_runtime.h>
#include <cuda_fp16.h>
#include <math.h>
#include <float.h>
#include <stdint.h>

#define NN   50000
#define NE   400000
#define NEF  450000    // NE + NN self loops
#define FIN  128
#define HC   256
#define NH   4
#define CD   64
#define EDIM 16
#define NGRP 64
#define NOUT 10

// ---------------- scratch (device globals; no allocation allowed) ----------
static __device__ __align__(16) float g_h[NN * HC];     // h = X @ W
static __device__ __align__(16) float g_add[NN * HC];   // residual accumulator
static __device__ float g_mea[NN * EDIM];               // mean edge_attr per dst
static __device__ int   g_degi[NN];
static __device__ float g_als[NN * NH];
static __device__ float g_ald[NN * NH];
static __device__ __align__(16) float g_alpha[(size_t)NEF * NH];
static __device__ float g_weeff3[3 * EDIM * NH];
static __device__ float g_t[NN];
static __device__ float g_score[NN];
static __device__ int   g_gstart[NGRP + 1];
static __device__ int   g_perm[NN];
// CSR by destination (built once, reused for all 3 layers)
static __device__ int   g_rowstart[NN + 1];
static __device__ int   g_cursor[NN];
static __device__ int   g_csrsrc[NE];
static __device__ int   g_csre[NE];
// pre-split weight planes (fp16 hi/lo), [k][n] row-major, 3 layers
static __device__ __align__(16) unsigned short g_wp_hi[3 * HC * HC];
static __device__ __align__(16) unsigned short g_wp_lo[3 * HC * HC];
// pre-split activation planes (fp16 hi/lo) -- GEMM A operand, [m][k]
static __device__ __align__(16) unsigned short g_ap_hi[NN * HC];
static __device__ __align__(16) unsigned short g_ap_lo[NN * HC];

// ---------------- helpers ----------------------------------------------------
__device__ __forceinline__ void split2(float v, unsigned short& hi, unsigned short& lo) {
    __half h = __float2half_rn(v);
    hi = __half_as_ushort(h);
    float r = v - __half2float(h);
    lo = __half_as_ushort(__float2half_rn(r));
}
__device__ __forceinline__ void cp16(uint32_t saddr, const void* g, int sz) {
    asm volatile("cp.async.cg.shared.global [%0], [%1], 16, %2;\n"
                 :: "r"(saddr), "l"(g), "r"(sz));
}
__device__ __forceinline__ void cp_commit() {
    asm volatile("cp.async.commit_group;\n");
}
template <int N>
__device__ __forceinline__ void cp_wait() {
    asm volatile("cp.async.wait_group %0;\n" :: "n"(N));
}

// ---------------- prologue: zero + degree+mean edge_attr (merged) -----------
__global__ void k_init0() {
    int i = blockIdx.x * blockDim.x + threadIdx.x;
    if (i < NN * EDIM) g_mea[i] = 0.f;
    if (i < NN) { g_degi[i] = 0; g_cursor[i] = 0; }
}
__global__ void k_measum(const int* __restrict__ dst, const float* __restrict__ ea) {
    int i = blockIdx.x * blockDim.x + threadIdx.x;
    if (i >= NE * EDIM) return;
    int e = i >> 4, j = i & 15;
    int d = dst[e];
    if (j == 0) atomicAdd(&g_degi[d], 1);
    atomicAdd(&g_mea[d * EDIM + j], ea[i]);
}
__global__ void k_meadiv() {
    int i = blockIdx.x * blockDim.x + threadIdx.x;
    if (i >= NN * EDIM) return;
    g_mea[i] /= fmaxf((float)g_degi[i >> 4], 1.f);
}

// ---------------- fast exclusive scan (shfl-based, 4096/chunk) --------------
__global__ void k_scan() {
    __shared__ int wsum[32];
    __shared__ int soff_s;
    int tid = threadIdx.x, lane = tid & 31, w = tid >> 5;
    if (tid == 0) soff_s = 0;
    __syncthreads();
    for (int chunk = 0; chunk < NN; chunk += 4096) {
        int idx = chunk + tid * 4;
        int v[4];
#pragma unroll
        for (int q = 0; q < 4; q++) v[q] = (idx + q < NN) ? g_degi[idx + q] : 0;
        int t = v[0] + v[1] + v[2] + v[3];
        int sc = t;
#pragma unroll
        for (int s = 1; s < 32; s <<= 1) {
            int u = __shfl_up_sync(0xFFFFFFFFu, sc, s);
            if (lane >= s) sc += u;
        }
        if (lane == 31) wsum[w] = sc;
        __syncthreads();
        if (w == 0) {
            int ws = wsum[lane];
#pragma unroll
            for (int s = 1; s < 32; s <<= 1) {
                int u = __shfl_up_sync(0xFFFFFFFFu, ws, s);
                if (lane >= s) ws += u;
            }
            wsum[lane] = ws;
        }
        __syncthreads();
        int base = soff_s + (w ? wsum[w - 1] : 0) + sc - t;
#pragma unroll
        for (int q = 0; q < 4; q++) {
            if (idx + q < NN) g_rowstart[idx + q] = base;
            base += v[q];
        }
        __syncthreads();
        if (tid == 0) soff_s += wsum[31];
        __syncthreads();
    }
    if (threadIdx.x == 0) g_rowstart[NN] = NE;
}

__global__ void k_fill(const int* __restrict__ src, const int* __restrict__ dst) {
    int e = blockIdx.x * blockDim.x + threadIdx.x;
    if (e >= NE) return;
    int d = dst[e];
    int pos = atomicAdd(&g_cursor[d], 1);
    int idx = g_rowstart[d] + pos;
    g_csrsrc[idx] = src[e];
    g_csre[idx] = e;
}

// ---------------- split ALL weight matrices upfront (fp16 hi/lo planes) -----
__global__ void k_prepw(const float* __restrict__ W1, const float* __restrict__ W2,
                        const float* __restrict__ W3) {
    int i = blockIdx.x * blockDim.x + threadIdx.x;
    const float* W; int idx; size_t off;
    if (i < FIN * HC)                      { W = W1; idx = i;                off = 0; }
    else if (i < FIN * HC + HC * HC)       { W = W2; idx = i - FIN * HC;     off = (size_t)HC * HC; }
    else if (i < FIN * HC + 2 * HC * HC)   { W = W3; idx = i - FIN * HC - HC * HC; off = (size_t)2 * HC * HC; }
    else return;
    unsigned short h, l;
    split2(W[idx], h, l);
    g_wp_hi[off + idx] = h; g_wp_lo[off + idx] = l;
}

// ---------------- per-layer: zero attention-logit accumulators --------------
__global__ void k_zals() {
    int i = blockIdx.x * blockDim.x + threadIdx.x;
    if (i < NN * NH) { g_als[i] = 0.f; g_ald[i] = 0.f; }
}

// ---------------- split layer-1 input x into fp16 planes --------------------
__global__ void k_splitx(const float* __restrict__ x) {
    int i = (blockIdx.x * blockDim.x + threadIdx.x) * 2;
    if (i >= NN * FIN) return;
    float2 v = *(const float2*)&x[i];
    unsigned short h0, l0, h1, l1;
    split2(v.x, h0, l0);
    split2(v.y, h1, l1);
    *(uint32_t*)&g_ap_hi[i] = (uint32_t)h0 | ((uint32_t)h1 << 16);
    *(uint32_t*)&g_ap_lo[i] = (uint32_t)l0 | ((uint32_t)l1 << 16);
}

// ---------------- tensor-core GEMM (fp16x3 ~= fp32), cp.async 2-stage -------
__device__ __forceinline__ void ldsm_x4(uint32_t& r0, uint32_t& r1, uint32_t& r2,
                                        uint32_t& r3, uint32_t addr) {
    asm volatile("ldmatrix.sync.aligned.m8n8.x4.shared.b16 {%0,%1,%2,%3}, [%4];"
                 : "=r"(r0), "=r"(r1), "=r"(r2), "=r"(r3) : "r"(addr));
}
__device__ __forceinline__ void ldsm_x2t(uint32_t& r0, uint32_t& r1, uint32_t addr) {
    asm volatile("ldmatrix.sync.aligned.m8n8.x2.trans.shared.b16 {%0,%1}, [%2];"
                 : "=r"(r0), "=r"(r1) : "r"(addr));
}
__device__ __forceinline__ void mma_f16(float* d, const uint32_t* a, const uint32_t* b) {
    asm volatile(
        "mma.sync.aligned.m16n8k16.row.col.f32.f16.f16.f32 "
        "{%0,%1,%2,%3}, {%4,%5,%6,%7}, {%8,%9}, {%0,%1,%2,%3};"
        : "+f"(d[0]), "+f"(d[1]), "+f"(d[2]), "+f"(d[3])
        : "r"(a[0]), "r"(a[1]), "r"(a[2]), "r"(a[3]), "r"(b[0]), "r"(b[1]));
}

#define ASTR 40
#define BSTR 136
#define A_PL (128 * ASTR)                 // shorts per A plane (5120)
#define B_PL (32 * BSTR)                  // shorts per B plane (4352)
#define STG  (2 * A_PL + 2 * B_PL)        // shorts per stage (18944)
#define SMEM_BYTES (2 * STG * 2)          // 75776 bytes

__global__ void __launch_bounds__(256, 2) k_gemm(int K,
                                                 const float* __restrict__ as_,
                                                 const float* __restrict__ ad_,
                                                 int l) {
    extern __shared__ unsigned short smem_u[];
    const unsigned short* gA[2] = {g_ap_hi, g_ap_lo};
    const unsigned short* gW[2] = {g_wp_hi + (size_t)l * HC * HC,
                                   g_wp_lo + (size_t)l * HC * HC};

    const int tid = threadIdx.x;
    const int lane = tid & 31;
    const int wid = tid >> 5;
    const int wm = (wid >> 2) * 64;
    const int wn = (wid & 3) * 32;
    const int rowBase = blockIdx.y * 128;
    const int n0 = blockIdx.x * 128;

    float acc[4][4][4];
#pragma unroll
    for (int i = 0; i < 4; i++)
#pragma unroll
        for (int j = 0; j < 4; j++)
#pragma unroll
            for (int q = 0; q < 4; q++) acc[i][j][q] = 0.f;

    const uint32_t sbase = (uint32_t)__cvta_generic_to_shared(smem_u);
    const int nk = K / 32;

    auto do_stage = [&](int k0, int s) {
        uint32_t sb = sbase + s * (STG * 2);
#pragma unroll
        for (int q = 0; q < 2; q++) {
            int c = tid * 2 + q;
            int row = c >> 2, col8 = (c & 3) * 8;
            int gm = rowBase + row;
            int sz = (gm < NN) ? 16 : 0;
            int gmc = (gm < NN) ? gm : (NN - 1);
            size_t goff = (size_t)gmc * K + k0 + col8;
            uint32_t so = sb + (row * ASTR + col8) * 2;
#pragma unroll
            for (int p = 0; p < 2; p++)
                cp16(so + p * (A_PL * 2), &gA[p][goff], sz);
        }
#pragma unroll
        for (int q = 0; q < 2; q++) {
            int c = tid * 2 + q;
            int row = c >> 4, col8 = (c & 15) * 8;
            size_t goff = (size_t)(k0 + row) * HC + n0 + col8;
            uint32_t so = sb + (2 * A_PL + row * BSTR + col8) * 2;
#pragma unroll
            for (int p = 0; p < 2; p++)
                cp16(so + p * (B_PL * 2), &gW[p][goff], 16);
        }
    };

    do_stage(0, 0);
    cp_commit();

    for (int kb = 0; kb < nk; kb++) {
        if (kb + 1 < nk) {
            do_stage((kb + 1) * 32, (kb + 1) & 1);
            cp_commit();
            cp_wait<1>();
        } else {
            cp_wait<0>();
        }
        __syncthreads();

        uint32_t sb = sbase + (kb & 1) * (STG * 2);
#pragma unroll
        for (int ks = 0; ks < 32; ks += 16) {
            uint32_t af[2][4][4], bb[4][2];
            int arow = lane & 15;
            int acol = ks + ((lane >> 4) << 3);
#pragma unroll
            for (int p = 0; p < 2; p++) {
                uint32_t pbase = sb + p * (A_PL * 2);
#pragma unroll
                for (int i = 0; i < 4; i++) {
                    uint32_t off = ((wm + i * 16 + arow) * ASTR + acol) * 2;
                    ldsm_x4(af[p][i][0], af[p][i][1], af[p][i][2], af[p][i][3], pbase + off);
                }
            }
            int brow = ks + (lane & 15);
            {
                uint32_t pbase = sb + (2 * A_PL) * 2;
#pragma unroll
                for (int j = 0; j < 4; j++) {
                    uint32_t off = (brow * BSTR + wn + j * 8) * 2;
                    ldsm_x2t(bb[j][0], bb[j][1], pbase + off);
                }
#pragma unroll
                for (int i = 0; i < 4; i++)
#pragma unroll
                    for (int j = 0; j < 4; j++) {
                        mma_f16(acc[i][j], af[0][i], bb[j]);
                        mma_f16(acc[i][j], af[1][i], bb[j]);
                    }
            }
            {
                uint32_t pbase = sb + (2 * A_PL + B_PL) * 2;
#pragma unroll
                for (int j = 0; j < 4; j++) {
                    uint32_t off = (brow * BSTR + wn + j * 8) * 2;
                    ldsm_x2t(bb[j][0], bb[j][1], pbase + off);
                }
#pragma unroll
                for (int i = 0; i < 4; i++)
#pragma unroll
                    for (int j = 0; j < 4; j++)
                        mma_f16(acc[i][j], af[0][i], bb[j]);
            }
        }
        __syncthreads();
    }

    // ---- epilogue: store h + fused attention logits (als/ald) ----
    const int head = (n0 + wn) >> 6;
    const int cbase = ((n0 + wn) & 63) + (lane & 3) * 2;
    float as8[4][2], ad8[4][2];
#pragma unroll
    for (int j = 0; j < 4; j++)
#pragma unroll
        for (int qb = 0; qb < 2; qb++) {
            int c = head * CD + cbase + j * 8 + qb;
            as8[j][qb] = as_[c];
            ad8[j][qb] = ad_[c];
        }

#pragma unroll
    for (int i = 0; i < 4; i++) {
        int r0 = rowBase + wm + i * 16 + (lane >> 2);
        float sa0 = 0.f, sd0 = 0.f, sa1 = 0.f, sd1 = 0.f;
#pragma unroll
        for (int j = 0; j < 4; j++) {
            int c = n0 + wn + j * 8 + (lane & 3) * 2;
            if (r0 < NN)
                *(float2*)&g_h[(size_t)r0 * HC + c] = make_float2(acc[i][j][0], acc[i][j][1]);
            if (r0 + 8 < NN)
                *(float2*)&g_h[(size_t)(r0 + 8) * HC + c] = make_float2(acc[i][j][2], acc[i][j][3]);
            sa0 += acc[i][j][0] * as8[j][0] + acc[i][j][1] * as8[j][1];
            sd0 += acc[i][j][0] * ad8[j][0] + acc[i][j][1] * ad8[j][1];
            sa1 += acc[i][j][2] * as8[j][0] + acc[i][j][3] * as8[j][1];
            sd1 += acc[i][j][2] * ad8[j][0] + acc[i][j][3] * ad8[j][1];
        }
#pragma unroll
        for (int s = 1; s < 4; s <<= 1) {
            sa0 += __shfl_xor_sync(0xFFFFFFFFu, sa0, s);
            sd0 += __shfl_xor_sync(0xFFFFFFFFu, sd0, s);
            sa1 += __shfl_xor_sync(0xFFFFFFFFu, sa1, s);
            sd1 += __shfl_xor_sync(0xFFFFFFFFu, sd1, s);
        }
        if ((lane & 3) == 0) {
            if (r0 < NN) {
                atomicAdd(&g_als[r0 * NH + head], sa0);
                atomicAdd(&g_ald[r0 * NH + head], sd0);
            }
            if (r0 + 8 < NN) {
                atomicAdd(&g_als[(r0 + 8) * NH + head], sa1);
                atomicAdd(&g_ald[(r0 + 8) * NH + head], sd1);
            }
        }
    }
}

// ---------------- effective edge weights (all 3 layers at once) -------------
__global__ void k_weeff3(const float* __restrict__ We1, const float* __restrict__ ae1,
                         const float* __restrict__ We2, const float* __restrict__ ae2,
                         const float* __restrict__ We3, const float* __restrict__ ae3) {
    int l = blockIdx.x;
    const float* We = (l == 0) ? We1 : (l == 1) ? We2 : We3;
    const float* ae = (l == 0) ? ae1 : (l == 1) ? ae2 : ae3;
    int tid = threadIdx.x;
    if (tid >= EDIM * NH) return;
    int d = tid >> 2, h = tid & 3;
    float s = 0.f;
    for (int c = 0; c < CD; c++) s += We[d * HC + h * CD + c] * ae[h * CD + c];
    g_weeff3[l * EDIM * NH + d * NH + h] = s;
}

// ---------------- edge logits (leaky relu'd) --------------------------------
__global__ void k_alpha(const int* __restrict__ src, const int* __restrict__ dst,
                        const float* __restrict__ ea, int l) {
    int e = blockIdx.x * blockDim.x + threadIdx.x;
    if (e >= NEF) return;
    const float* weeff = &g_weeff3[l * EDIM * NH];
    int s, d;
    const float* eap;
    if (e < NE) { s = src[e]; d = dst[e]; eap = ea + (size_t)e * EDIM; }
    else        { s = d = e - NE; eap = g_mea + (size_t)(e - NE) * EDIM; }
    float ev[16];
    *(float4*)&ev[0]  = *(const float4*)&eap[0];
    *(float4*)&ev[4]  = *(const float4*)&eap[4];
    *(float4*)&ev[8]  = *(const float4*)&eap[8];
    *(float4*)&ev[12] = *(const float4*)&eap[12];
    float ale[NH] = {0.f, 0.f, 0.f, 0.f};
#pragma unroll
    for (int dd = 0; dd < EDIM; dd++) {
        float v = ev[dd];
#pragma unroll
        for (int h = 0; h < NH; h++) ale[h] += v * weeff[dd * NH + h];
    }
    float4 out;
    float* op = (float*)&out;
#pragma unroll
    for (int h = 0; h < NH; h++) {
        float a = g_als[s * NH + h] + g_ald[d * NH + h] + ale[h];
        op[h] = (a > 0.f) ? a : 0.2f * a;
    }
    *(float4*)&g_alpha[(size_t)e * NH] = out;
}

// ---------------- gather aggregation: warp per dst, online softmax ----------
// mode: 0 = first layer, 1 = middle, 2 = last (fused SAGPool dots, no planes)
__global__ void k_gather(const float* __restrict__ b, int mode,
                         const float* __restrict__ wrel,
                         const float* __restrict__ wroot,
                         const float* __restrict__ brel) {
    int d = blockIdx.x * (blockDim.x >> 5) + (threadIdx.x >> 5);
    int lane = threadIdx.x & 31;
    if (d >= NN) return;
    int h = lane >> 3;
    float acc[8] = {};
    float m = -FLT_MAX, den = 0.f;
    int beg = g_rowstart[d], end = g_rowstart[d + 1];
    for (int i = beg; i < end; i++) {
        int s = g_csrsrc[i];
        int e = g_csre[i];
        float a = g_alpha[(size_t)e * NH + h];
        float mnew = fmaxf(m, a);
        float scale = __expf(m - mnew);
        float ex = __expf(a - mnew);
        den = den * scale + ex;
        const float4* hp = (const float4*)&g_h[(size_t)s * HC + lane * 8];
        float4 v0 = hp[0], v1 = hp[1];
        acc[0] = acc[0] * scale + ex * v0.x; acc[1] = acc[1] * scale + ex * v0.y;
        acc[2] = acc[2] * scale + ex * v0.z; acc[3] = acc[3] * scale + ex * v0.w;
        acc[4] = acc[4] * scale + ex * v1.x; acc[5] = acc[5] * scale + ex * v1.y;
        acc[6] = acc[6] * scale + ex * v1.z; acc[7] = acc[7] * scale + ex * v1.w;
        m = mnew;
    }
    {   // self loop (src = dst = d)
        float a = g_alpha[(size_t)(NE + d) * NH + h];
        float mnew = fmaxf(m, a);
        float scale = __expf(m - mnew);
        float ex = __expf(a - mnew);
        den = den * scale + ex;
        const float4* hp = (const float4*)&g_h[(size_t)d * HC + lane * 8];
        float4 v0 = hp[0], v1 = hp[1];
        acc[0] = acc[0] * scale + ex * v0.x; acc[1] = acc[1] * scale + ex * v0.y;
        acc[2] = acc[2] * scale + ex * v0.z; acc[3] = acc[3] * scale + ex * v0.w;
        acc[4] = acc[4] * scale + ex * v1.x; acc[5] = acc[5] * scale + ex * v1.y;
        acc[6] = acc[6] * scale + ex * v1.z; acc[7] = acc[7] * scale + ex * v1.w;
    }
    float inv = 1.f / (den + 1e-16f);
    int col = lane * 8;
    float o[8];
#pragma unroll
    for (int j = 0; j < 8; j++) {
        float v = acc[j] * inv + b[col + j];
        o[j] = fmaxf(v, 0.f);
    }
    size_t base = (size_t)d * HC + col;
    if (mode != 2) {
        // split output into fp16 planes for the next GEMM
        unsigned short hs[8], ls[8];
#pragma unroll
        for (int j = 0; j < 8; j++) split2(o[j], hs[j], ls[j]);
        uint4 uh, ul;
        uh.x = (uint32_t)hs[0] | ((uint32_t)hs[1] << 16);
        uh.y = (uint32_t)hs[2] | ((uint32_t)hs[3] << 16);
        uh.z = (uint32_t)hs[4] | ((uint32_t)hs[5] << 16);
        uh.w = (uint32_t)hs[6] | ((uint32_t)hs[7] << 16);
        ul.x = (uint32_t)ls[0] | ((uint32_t)ls[1] << 16);
        ul.y = (uint32_t)ls[2] | ((uint32_t)ls[3] << 16);
        ul.z = (uint32_t)ls[4] | ((uint32_t)ls[5] << 16);
        ul.w = (uint32_t)ls[6] | ((uint32_t)ls[7] << 16);
        *(uint4*)&g_ap_hi[base] = uh;
        *(uint4*)&g_ap_lo[base] = ul;
    }
    float na[8];
    if (mode == 0) {
#pragma unroll
        for (int j = 0; j < 8; j++) na[j] = o[j];
    } else {
        float4 a0 = *(float4*)&g_add[base], a1 = *(float4*)&g_add[base + 4];
        na[0] = a0.x + o[0]; na[1] = a0.y + o[1]; na[2] = a0.z + o[2]; na[3] = a0.w + o[3];
        na[4] = a1.x + o[4]; na[5] = a1.y + o[5]; na[6] = a1.z + o[6]; na[7] = a1.w + o[7];
    }
    *(float4*)&g_add[base]     = *(float4*)&na[0];
    *(float4*)&g_add[base + 4] = *(float4*)&na[4];

    if (mode == 2) {
        // fused SAGPool row dots: t = add.wrel, score = add.wroot + brel
        float t = 0.f, r = 0.f;
#pragma unroll
        for (int j = 0; j < 8; j++) {
            t += na[j] * wrel[col + j];
            r += na[j] * wroot[col + j];
        }
#pragma unroll
        for (int s = 16; s > 0; s >>= 1) {
            t += __shfl_xor_sync(0xFFFFFFFFu, t, s);
            r += __shfl_xor_sync(0xFFFFFFFFu, r, s);
        }
        if (lane == 0) { g_t[d] = t; g_score[d] = r + brel[0]; }
    }
}

// deterministic CSR gather (double accumulate)
__global__ void k_scoreagg() {
    int d = blockIdx.x * blockDim.x + threadIdx.x;
    if (d >= NN) return;
    double s = 0.0;
    int beg = g_rowstart[d], end = g_rowstart[d + 1];
    for (int i = beg; i < end; i++) s += (double)g_t[g_csrsrc[i]];
    g_score[d] += (float)s;
}

// ---------------- group boundaries (batch is sorted) --------------------------
__global__ void k_gstart(const int* __restrict__ batch) {
    int n = blockIdx.x * blockDim.x + threadIdx.x;
    if (n >= NN) return;
    int b = batch[n];
    int prev = (n == 0) ? -1 : batch[n - 1];
    for (int g = prev + 1; g <= b; g++) g_gstart[g] = n;
    if (n == NN - 1) {
        for (int g = b + 1; g <= NGRP; g++) g_gstart[g] = NN;
    }
}

// ---------------- per-group bitonic sort (descending score, tie: asc index) --
#define SORTP 1024
__global__ void k_sort() {
    __shared__ float sk[SORTP];
    __shared__ int   sv[SORTP];
    int g = blockIdx.x;
    int start = g_gstart[g], end = g_gstart[g + 1];
    int sz = end - start;
    if (sz > SORTP) sz = SORTP;
    for (int i = threadIdx.x; i < SORTP; i += blockDim.x) {
        if (i < sz) { sk[i] = g_score[start + i]; sv[i] = start + i; }
        else        { sk[i] = -FLT_MAX; sv[i] = 0x7FFFFFFF; }
    }
    __syncthreads();
    for (int k = 2; k <= SORTP; k <<= 1) {
        for (int j = k >> 1; j > 0; j >>= 1) {
            for (int i = threadIdx.x; i < SORTP; i += blockDim.x) {
                int ixj = i ^ j;
                if (ixj > i) {
                    float ki = sk[i], kj = sk[ixj];
                    int vi = sv[i], vj = sv[ixj];
                    bool before = (kj > ki) || (kj == ki && vj < vi);
                    bool dir = ((i & k) == 0);
                    if (before == dir) {
                        sk[i] = kj; sk[ixj] = ki;
                        sv[i] = vj; sv[ixj] = vi;
                    }
                }
            }
            __syncthreads();
        }
    }
    for (int i = threadIdx.x; i < sz; i += blockDim.x) g_perm[start + i] = sv[i];
}

// ---------------- final: gate + 256->10 GEMV + sigmoid ------------------------
__global__ void k_final(const float* __restrict__ wl, const float* __restrict__ bl,
                        float* __restrict__ out) {
    __shared__ float swl[HC * NOUT];
    for (int i = threadIdx.x; i < HC * NOUT; i += blockDim.x) swl[i] = wl[i];
    __syncthreads();
    int pos = blockIdx.x * 8 + (threadIdx.x >> 5);
    int lane = threadIdx.x & 31;
    if (pos >= NN) return;
    int p = g_perm[pos];
    float ts = tanhf(g_score[p]);
    float acc[NOUT];
#pragma unroll
    for (int o = 0; o < NOUT; o++) acc[o] = 0.f;
    size_t base = (size_t)p * HC + lane * 8;
#pragma unroll
    for (int jj = 0; jj < 8; jj++) {
        float v = g_add[base + jj] * ts;
        const float* wrow = &swl[(lane * 8 + jj) * NOUT];
#pragma unroll
        for (int o = 0; o < NOUT; o++) acc[o] += v * wrow[o];
    }
#pragma unroll
    for (int s = 16; s > 0; s >>= 1)
#pragma unroll
        for (int o = 0; o < NOUT; o++) acc[o] += __shfl_xor_sync(0xFFFFFFFFu, acc[o], s);
    if (lane == 0) {
#pragma unroll
        for (int o = 0; o < NOUT; o++)
            out[(size_t)pos * NOUT + o] = 1.f / (1.f + expf(-(acc[o] + bl[o])));
    }
}

// ---------------- launch ------------------------------------------------------
extern "C" void kernel_launch(void* const* d_in, const int* in_sizes, int n_in,
                              void* d_out, int out_size) {
    const float* x     = (const float*)d_in[0];
    const int*   eidx  = (const int*)d_in[1];
    const int*   batch = (const int*)d_in[2];
    const float* ea    = (const float*)d_in[3];
    const float* W[3]  = {(const float*)d_in[4],  (const float*)d_in[10], (const float*)d_in[16]};
    const float* AS[3] = {(const float*)d_in[5],  (const float*)d_in[11], (const float*)d_in[17]};
    const float* AD[3] = {(const float*)d_in[6],  (const float*)d_in[12], (const float*)d_in[18]};
    const float* WE[3] = {(const float*)d_in[7],  (const float*)d_in[13], (const float*)d_in[19]};
    const float* AE[3] = {(const float*)d_in[8],  (const float*)d_in[14], (const float*)d_in[20]};
    const float* B[3]  = {(const float*)d_in[9],  (const float*)d_in[15], (const float*)d_in[21]};
    const float* wrel  = (const float*)d_in[22];
    const float* brel  = (const float*)d_in[23];
    const float* wroot = (const float*)d_in[24];
    const float* wl    = (const float*)d_in[25];
    const float* bl    = (const float*)d_in[26];

    const int* src = eidx;
    const int* dst = eidx + NE;

    static cudaStream_t s2 = nullptr;
    static cudaEvent_t evA = nullptr, evB = nullptr;
    if (!s2) {
        cudaStreamCreateWithFlags(&s2, cudaStreamNonBlocking);
        cudaEventCreateWithFlags(&evA, cudaEventDisableTiming);
        cudaEventCreateWithFlags(&evB, cudaEventDisableTiming);
        cudaFuncSetAttribute(k_gemm, cudaFuncAttributeMaxDynamicSharedMemorySize, SMEM_BYTES);
    }

    const int T = 256;

    // ---- fork: CSR/prologue chain on s2, GEMM prep on primary ----
    cudaEventRecord(evA, 0);
    cudaStreamWaitEvent(s2, evA, 0);
    k_init0<<<(NN * EDIM + T - 1) / T, T, 0, s2>>>();
    k_measum<<<(NE * EDIM + T - 1) / T, T, 0, s2>>>(dst, ea);
    k_meadiv<<<(NN * EDIM + T - 1) / T, T, 0, s2>>>();
    k_scan<<<1, 1024, 0, s2>>>();
    k_fill<<<(NE + T - 1) / T, T, 0, s2>>>(src, dst);
    k_gstart<<<(NN + T - 1) / T, T, 0, s2>>>(batch);
    cudaEventRecord(evB, s2);

    // primary stream: weight/input prep + layer-0 GEMM (independent of CSR)
    k_weeff3<<<3, 64>>>(WE[0], AE[0], WE[1], AE[1], WE[2], AE[2]);
    k_splitx<<<(NN * FIN / 2 + T - 1) / T, T>>>(x);
    k_prepw<<<(FIN * HC + 2 * HC * HC + T - 1) / T, T>>>(W[0], W[1], W[2]);

    for (int l = 0; l < 3; l++) {
        int K = (l == 0) ? FIN : HC;
        k_zals<<<(NN * NH + T - 1) / T, T>>>();
        k_gemm<<<dim3(HC / 128, (NN + 127) / 128), T, SMEM_BYTES>>>(K, AS[l], AD[l], l);
        if (l == 0) cudaStreamWaitEvent(0, evB, 0);  // join: alpha/gather need CSR + mea
        k_alpha<<<(NEF + T - 1) / T, T>>>(src, dst, ea, l);
        k_gather<<<(NN + 7) / 8, T>>>(B[l], (l == 0) ? 0 : (l == 2) ? 2 : 1,
                                      wrel, wroot, brel);
    }

    // SAGPool score (deterministic CSR aggregation; t/score already computed)
    k_scoreagg<<<(NN + T - 1) / T, T>>>();

    // per-graph sort + final head
    k_sort<<<NGRP, 512>>>();
    k_final<<<(NN + 7) / 8, T>>>(wl, bl, (float*)d_out);
}

// round 14
// speedup vs baseline: 1.0882x; 1.0563x over previous
#include <cuda_runtime.h>
#include <cuda_fp16.h>
#include <math.h>
#include <float.h>
#include <stdint.h>

#define NN   50000
#define NE   400000
#define NEF  450000    // NE + NN self loops
#define FIN  128
#define HC   256
#define NH   4
#define CD   64
#define EDIM 16
#define NGRP 64
#define NOUT 10
#define SCANB 13       // scan blocks (13 * 4096 >= NN)

// ---------------- scratch (device globals; no allocation allowed) ----------
static __device__ __align__(16) float g_h[NN * HC];     // h = X @ W
static __device__ __align__(16) float g_add[NN * HC];   // residual accumulator
static __device__ float g_mea[NN * EDIM];               // mean edge_attr per dst
static __device__ int   g_degi[NN];
static __device__ float g_als[NN * NH];
static __device__ float g_ald[NN * NH];
// CSR-ordered edge logits (pre-leaky), all 3 layers: [l][csr_pos][h]
static __device__ __align__(16) float g_alecsr[(size_t)3 * NEF * NH];
static __device__ float g_weeff3[3 * EDIM * NH];
static __device__ float g_t[NN];
static __device__ float g_score[NN];
static __device__ int   g_gstart[NGRP + 1];
static __device__ int   g_perm[NN];
// CSR by destination (built once, reused for all 3 layers)
static __device__ int   g_rowstart[NN + 1];
static __device__ int   g_cursor[NN];
static __device__ int   g_csrsrc[NE];
static __device__ int   g_csre[NE];
static __device__ int   g_csrpos[NE];
static __device__ int   g_bsum[SCANB];
static __device__ int   g_boff[SCANB];
// pre-split weight planes (fp16 hi/lo), [k][n] row-major, 3 layers
static __device__ __align__(16) unsigned short g_wp_hi[3 * HC * HC];
static __device__ __align__(16) unsigned short g_wp_lo[3 * HC * HC];
// pre-split activation planes (fp16 hi/lo) -- GEMM A operand, [m][k]
static __device__ __align__(16) unsigned short g_ap_hi[NN * HC];
static __device__ __align__(16) unsigned short g_ap_lo[NN * HC];

// ---------------- helpers ----------------------------------------------------
__device__ __forceinline__ void split2(float v, unsigned short& hi, unsigned short& lo) {
    __half h = __float2half_rn(v);
    hi = __half_as_ushort(h);
    float r = v - __half2float(h);
    lo = __half_as_ushort(__float2half_rn(r));
}
__device__ __forceinline__ void cp16(uint32_t saddr, const void* g, int sz) {
    asm volatile("cp.async.cg.shared.global [%0], [%1], 16, %2;\n"
                 :: "r"(saddr), "l"(g), "r"(sz));
}
__device__ __forceinline__ void cp_commit() {
    asm volatile("cp.async.commit_group;\n");
}
template <int N>
__device__ __forceinline__ void cp_wait() {
    asm volatile("cp.async.wait_group %0;\n" :: "n"(N));
}

// ---------------- prologue ----------------------------------------------------
__global__ void k_init0() {
    int i = blockIdx.x * blockDim.x + threadIdx.x;
    if (i < NN) { g_degi[i] = 0; g_cursor[i] = 0; }
}
__global__ void k_deg(const int* __restrict__ dst) {
    int e = blockIdx.x * blockDim.x + threadIdx.x;
    if (e < NE) atomicAdd(&g_degi[dst[e]], 1);
}

// ---------------- 3-phase exclusive scan of degrees -------------------------
__global__ void k_scan1() {
    __shared__ int wsum[32];
    int tid = threadIdx.x, lane = tid & 31, w = tid >> 5;
    int idx = blockIdx.x * 4096 + tid * 4;
    int v[4];
#pragma unroll
    for (int q = 0; q < 4; q++) v[q] = (idx + q < NN) ? g_degi[idx + q] : 0;
    int t = v[0] + v[1] + v[2] + v[3];
    int sc = t;
#pragma unroll
    for (int s = 1; s < 32; s <<= 1) {
        int u = __shfl_up_sync(0xFFFFFFFFu, sc, s);
        if (lane >= s) sc += u;
    }
    if (lane == 31) wsum[w] = sc;
    __syncthreads();
    if (w == 0) {
        int ws = wsum[lane];
#pragma unroll
        for (int s = 1; s < 32; s <<= 1) {
            int u = __shfl_up_sync(0xFFFFFFFFu, ws, s);
            if (lane >= s) ws += u;
        }
        wsum[lane] = ws;
    }
    __syncthreads();
    int base = (w ? wsum[w - 1] : 0) + sc - t;
#pragma unroll
    for (int q = 0; q < 4; q++) {
        if (idx + q < NN) g_rowstart[idx + q] = base;
        base += v[q];
    }
    if (tid == 0) g_bsum[blockIdx.x] = wsum[31];
}
__global__ void k_scan2() {
    int lane = threadIdx.x;
    int v = (lane < SCANB) ? g_bsum[lane] : 0;
    int sc = v;
#pragma unroll
    for (int s = 1; s < 32; s <<= 1) {
        int u = __shfl_up_sync(0xFFFFFFFFu, sc, s);
        if (lane >= s) sc += u;
    }
    if (lane < SCANB) g_boff[lane] = sc - v;
    if (lane == 0) g_rowstart[NN] = NE;
}
__global__ void k_scan3() {
    int off = g_boff[blockIdx.x];
    if (off == 0) return;
    int idx = blockIdx.x * 4096 + threadIdx.x * 4;
#pragma unroll
    for (int q = 0; q < 4; q++)
        if (idx + q < NN) g_rowstart[idx + q] += off;
}

__global__ void k_fill(const int* __restrict__ src, const int* __restrict__ dst) {
    int e = blockIdx.x * blockDim.x + threadIdx.x;
    if (e >= NE) return;
    int d = dst[e];
    int pos = atomicAdd(&g_cursor[d], 1);
    int idx = g_rowstart[d] + pos;
    g_csrsrc[idx] = src[e];
    g_csre[idx] = e;
    g_csrpos[e] = idx;
}

// ---------------- mean edge_attr via CSR (no atomics) ------------------------
__global__ void k_meacsr(const float* __restrict__ ea) {
    int d = blockIdx.x * 16 + (threadIdx.x >> 4);
    int lane16 = threadIdx.x & 15;
    if (d >= NN) return;
    int beg = g_rowstart[d], end = g_rowstart[d + 1];
    float s = 0.f;
    for (int i = beg; i < end; i++) {
        int e = g_csre[i];
        s += ea[(size_t)e * EDIM + lane16];
    }
    float dg = (float)(end - beg);
    g_mea[d * EDIM + lane16] = s / fmaxf(dg, 1.f);
}

// ---------------- effective edge weights (all 3 layers at once) -------------
__global__ void k_weeff3(const float* __restrict__ We1, const float* __restrict__ ae1,
                         const float* __restrict__ We2, const float* __restrict__ ae2,
                         const float* __restrict__ We3, const float* __restrict__ ae3) {
    int l = blockIdx.x;
    const float* We = (l == 0) ? We1 : (l == 1) ? We2 : We3;
    const float* ae = (l == 0) ? ae1 : (l == 1) ? ae2 : ae3;
    int tid = threadIdx.x;
    if (tid >= EDIM * NH) return;
    int d = tid >> 2, h = tid & 3;
    float s = 0.f;
    for (int c = 0; c < CD; c++) s += We[d * HC + h * CD + c] * ae[h * CD + c];
    g_weeff3[l * EDIM * NH + d * NH + h] = s;
}

// ---------------- edge-attr logits for all 3 layers, CSR-ordered ------------
__global__ void k_ale3(const float* __restrict__ ea) {
    int e = blockIdx.x * blockDim.x + threadIdx.x;
    if (e >= NEF) return;
    const float* eap;
    int pos;
    if (e < NE) { eap = ea + (size_t)e * EDIM; pos = g_csrpos[e]; }
    else        { eap = g_mea + (size_t)(e - NE) * EDIM; pos = e; }
    float ev[16];
    *(float4*)&ev[0]  = *(const float4*)&eap[0];
    *(float4*)&ev[4]  = *(const float4*)&eap[4];
    *(float4*)&ev[8]  = *(const float4*)&eap[8];
    *(float4*)&ev[12] = *(const float4*)&eap[12];
#pragma unroll
    for (int l = 0; l < 3; l++) {
        const float* weeff = &g_weeff3[l * EDIM * NH];
        float ale[NH] = {0.f, 0.f, 0.f, 0.f};
#pragma unroll
        for (int dd = 0; dd < EDIM; dd++) {
            float v = ev[dd];
#pragma unroll
            for (int h = 0; h < NH; h++) ale[h] += v * weeff[dd * NH + h];
        }
        *(float4*)&g_alecsr[((size_t)l * NEF + pos) * NH] = *(float4*)&ale[0];
    }
}

// ---------------- split ALL weight matrices upfront (fp16 hi/lo planes) -----
__global__ void k_prepw(const float* __restrict__ W1, const float* __restrict__ W2,
                        const float* __restrict__ W3) {
    int i = blockIdx.x * blockDim.x + threadIdx.x;
    const float* W; int idx; size_t off;
    if (i < FIN * HC)                      { W = W1; idx = i;                off = 0; }
    else if (i < FIN * HC + HC * HC)       { W = W2; idx = i - FIN * HC;     off = (size_t)HC * HC; }
    else if (i < FIN * HC + 2 * HC * HC)   { W = W3; idx = i - FIN * HC - HC * HC; off = (size_t)2 * HC * HC; }
    else return;
    unsigned short h, l;
    split2(W[idx], h, l);
    g_wp_hi[off + idx] = h; g_wp_lo[off + idx] = l;
}

// ---------------- per-layer: zero attention-logit accumulators --------------
__global__ void k_zals() {
    int i = blockIdx.x * blockDim.x + threadIdx.x;
    if (i < NN * NH) { g_als[i] = 0.f; g_ald[i] = 0.f; }
}

// ---------------- split layer-1 input x into fp16 planes --------------------
__global__ void k_splitx(const float* __restrict__ x) {
    int i = (blockIdx.x * blockDim.x + threadIdx.x) * 2;
    if (i >= NN * FIN) return;
    float2 v = *(const float2*)&x[i];
    unsigned short h0, l0, h1, l1;
    split2(v.x, h0, l0);
    split2(v.y, h1, l1);
    *(uint32_t*)&g_ap_hi[i] = (uint32_t)h0 | ((uint32_t)h1 << 16);
    *(uint32_t*)&g_ap_lo[i] = (uint32_t)l0 | ((uint32_t)l1 << 16);
}

// ---------------- tensor-core GEMM (fp16x3 ~= fp32), cp.async 2-stage -------
__device__ __forceinline__ void ldsm_x4(uint32_t& r0, uint32_t& r1, uint32_t& r2,
                                        uint32_t& r3, uint32_t addr) {
    asm volatile("ldmatrix.sync.aligned.m8n8.x4.shared.b16 {%0,%1,%2,%3}, [%4];"
                 : "=r"(r0), "=r"(r1), "=r"(r2), "=r"(r3) : "r"(addr));
}
__device__ __forceinline__ void ldsm_x2t(uint32_t& r0, uint32_t& r1, uint32_t addr) {
    asm volatile("ldmatrix.sync.aligned.m8n8.x2.trans.shared.b16 {%0,%1}, [%2];"
                 : "=r"(r0), "=r"(r1) : "r"(addr));
}
__device__ __forceinline__ void mma_f16(float* d, const uint32_t* a, const uint32_t* b) {
    asm volatile(
        "mma.sync.aligned.m16n8k16.row.col.f32.f16.f16.f32 "
        "{%0,%1,%2,%3}, {%4,%5,%6,%7}, {%8,%9}, {%0,%1,%2,%3};"
        : "+f"(d[0]), "+f"(d[1]), "+f"(d[2]), "+f"(d[3])
        : "r"(a[0]), "r"(a[1]), "r"(a[2]), "r"(a[3]), "r"(b[0]), "r"(b[1]));
}

#define ASTR 40
#define BSTR 136
#define A_PL (128 * ASTR)                 // shorts per A plane (5120)
#define B_PL (32 * BSTR)                  // shorts per B plane (4352)
#define STG  (2 * A_PL + 2 * B_PL)        // shorts per stage (18944)
#define SMEM_BYTES (2 * STG * 2)          // 75776 bytes

__global__ void __launch_bounds__(256, 2) k_gemm(int K,
                                                 const float* __restrict__ as_,
                                                 const float* __restrict__ ad_,
                                                 int l) {
    extern __shared__ unsigned short smem_u[];
    const unsigned short* gA[2] = {g_ap_hi, g_ap_lo};
    const unsigned short* gW[2] = {g_wp_hi + (size_t)l * HC * HC,
                                   g_wp_lo + (size_t)l * HC * HC};

    const int tid = threadIdx.x;
    const int lane = tid & 31;
    const int wid = tid >> 5;
    const int wm = (wid >> 2) * 64;
    const int wn = (wid & 3) * 32;
    const int rowBase = blockIdx.y * 128;
    const int n0 = blockIdx.x * 128;

    float acc[4][4][4];
#pragma unroll
    for (int i = 0; i < 4; i++)
#pragma unroll
        for (int j = 0; j < 4; j++)
#pragma unroll
            for (int q = 0; q < 4; q++) acc[i][j][q] = 0.f;

    const uint32_t sbase = (uint32_t)__cvta_generic_to_shared(smem_u);
    const int nk = K / 32;

    auto do_stage = [&](int k0, int s) {
        uint32_t sb = sbase + s * (STG * 2);
#pragma unroll
        for (int q = 0; q < 2; q++) {
            int c = tid * 2 + q;
            int row = c >> 2, col8 = (c & 3) * 8;
            int gm = rowBase + row;
            int sz = (gm < NN) ? 16 : 0;
            int gmc = (gm < NN) ? gm : (NN - 1);
            size_t goff = (size_t)gmc * K + k0 + col8;
            uint32_t so = sb + (row * ASTR + col8) * 2;
#pragma unroll
            for (int p = 0; p < 2; p++)
                cp16(so + p * (A_PL * 2), &gA[p][goff], sz);
        }
#pragma unroll
        for (int q = 0; q < 2; q++) {
            int c = tid * 2 + q;
            int row = c >> 4, col8 = (c & 15) * 8;
            size_t goff = (size_t)(k0 + row) * HC + n0 + col8;
            uint32_t so = sb + (2 * A_PL + row * BSTR + col8) * 2;
#pragma unroll
            for (int p = 0; p < 2; p++)
                cp16(so + p * (B_PL * 2), &gW[p][goff], 16);
        }
    };

    do_stage(0, 0);
    cp_commit();

    for (int kb = 0; kb < nk; kb++) {
        if (kb + 1 < nk) {
            do_stage((kb + 1) * 32, (kb + 1) & 1);
            cp_commit();
            cp_wait<1>();
        } else {
            cp_wait<0>();
        }
        __syncthreads();

        uint32_t sb = sbase + (kb & 1) * (STG * 2);
#pragma unroll
        for (int ks = 0; ks < 32; ks += 16) {
            uint32_t af[2][4][4], bb[4][2];
            int arow = lane & 15;
            int acol = ks + ((lane >> 4) << 3);
#pragma unroll
            for (int p = 0; p < 2; p++) {
                uint32_t pbase = sb + p * (A_PL * 2);
#pragma unroll
                for (int i = 0; i < 4; i++) {
                    uint32_t off = ((wm + i * 16 + arow) * ASTR + acol) * 2;
                    ldsm_x4(af[p][i][0], af[p][i][1], af[p][i][2], af[p][i][3], pbase + off);
                }
            }
            int brow = ks + (lane & 15);
            {
                uint32_t pbase = sb + (2 * A_PL) * 2;
#pragma unroll
                for (int j = 0; j < 4; j++) {
                    uint32_t off = (brow * BSTR + wn + j * 8) * 2;
                    ldsm_x2t(bb[j][0], bb[j][1], pbase + off);
                }
#pragma unroll
                for (int i = 0; i < 4; i++)
#pragma unroll
                    for (int j = 0; j < 4; j++) {
                        mma_f16(acc[i][j], af[0][i], bb[j]);
                        mma_f16(acc[i][j], af[1][i], bb[j]);
                    }
            }
            {
                uint32_t pbase = sb + (2 * A_PL + B_PL) * 2;
#pragma unroll
                for (int j = 0; j < 4; j++) {
                    uint32_t off = (brow * BSTR + wn + j * 8) * 2;
                    ldsm_x2t(bb[j][0], bb[j][1], pbase + off);
                }
#pragma unroll
                for (int i = 0; i < 4; i++)
#pragma unroll
                    for (int j = 0; j < 4; j++)
                        mma_f16(acc[i][j], af[0][i], bb[j]);
            }
        }
        __syncthreads();
    }

    // ---- epilogue: store h + fused attention logits (als/ald) ----
    const int head = (n0 + wn) >> 6;
    const int cbase = ((n0 + wn) & 63) + (lane & 3) * 2;
    float as8[4][2], ad8[4][2];
#pragma unroll
    for (int j = 0; j < 4; j++)
#pragma unroll
        for (int qb = 0; qb < 2; qb++) {
            int c = head * CD + cbase + j * 8 + qb;
            as8[j][qb] = as_[c];
            ad8[j][qb] = ad_[c];
        }

#pragma unroll
    for (int i = 0; i < 4; i++) {
        int r0 = rowBase + wm + i * 16 + (lane >> 2);
        float sa0 = 0.f, sd0 = 0.f, sa1 = 0.f, sd1 = 0.f;
#pragma unroll
        for (int j = 0; j < 4; j++) {
            int c = n0 + wn + j * 8 + (lane & 3) * 2;
            if (r0 < NN)
                *(float2*)&g_h[(size_t)r0 * HC + c] = make_float2(acc[i][j][0], acc[i][j][1]);
            if (r0 + 8 < NN)
                *(float2*)&g_h[(size_t)(r0 + 8) * HC + c] = make_float2(acc[i][j][2], acc[i][j][3]);
            sa0 += acc[i][j][0] * as8[j][0] + acc[i][j][1] * as8[j][1];
            sd0 += acc[i][j][0] * ad8[j][0] + acc[i][j][1] * ad8[j][1];
            sa1 += acc[i][j][2] * as8[j][0] + acc[i][j][3] * as8[j][1];
            sd1 += acc[i][j][2] * ad8[j][0] + acc[i][j][3] * ad8[j][1];
        }
#pragma unroll
        for (int s = 1; s < 4; s <<= 1) {
            sa0 += __shfl_xor_sync(0xFFFFFFFFu, sa0, s);
            sd0 += __shfl_xor_sync(0xFFFFFFFFu, sd0, s);
            sa1 += __shfl_xor_sync(0xFFFFFFFFu, sa1, s);
            sd1 += __shfl_xor_sync(0xFFFFFFFFu, sd1, s);
        }
        if ((lane & 3) == 0) {
            if (r0 < NN) {
                atomicAdd(&g_als[r0 * NH + head], sa0);
                atomicAdd(&g_ald[r0 * NH + head], sd0);
            }
            if (r0 + 8 < NN) {
                atomicAdd(&g_als[(r0 + 8) * NH + head], sa1);
                atomicAdd(&g_ald[(r0 + 8) * NH + head], sd1);
            }
        }
    }
}

// ---------------- gather: warp per dst, inline logits + online softmax ------
// mode: 0 = first layer, 1 = middle, 2 = last (fused SAGPool dots, no planes)
__global__ void k_gather(const float* __restrict__ b, int mode, int l,
                         const float* __restrict__ wrel,
                         const float* __restrict__ wroot,
                         const float* __restrict__ brel) {
    int d = blockIdx.x * (blockDim.x >> 5) + (threadIdx.x >> 5);
    int lane = threadIdx.x & 31;
    if (d >= NN) return;
    int h = lane >> 3;
    const float* alec = g_alecsr + (size_t)l * NEF * NH;
    float aldh = g_ald[d * NH + h];
    float acc[8] = {};
    float m = -FLT_MAX, den = 0.f;
    int beg = g_rowstart[d], end = g_rowstart[d + 1];
    for (int i = beg; i < end; i++) {
        int s = g_csrsrc[i];
        float a = g_als[s * NH + h] + aldh + alec[(size_t)i * NH + h];
        a = (a > 0.f) ? a : 0.2f * a;
        float mnew = fmaxf(m, a);
        float scale = __expf(m - mnew);
        float ex = __expf(a - mnew);
        den = den * scale + ex;
        const float4* hp = (const float4*)&g_h[(size_t)s * HC + lane * 8];
        float4 v0 = hp[0], v1 = hp[1];
        acc[0] = acc[0] * scale + ex * v0.x; acc[1] = acc[1] * scale + ex * v0.y;
        acc[2] = acc[2] * scale + ex * v0.z; acc[3] = acc[3] * scale + ex * v0.w;
        acc[4] = acc[4] * scale + ex * v1.x; acc[5] = acc[5] * scale + ex * v1.y;
        acc[6] = acc[6] * scale + ex * v1.z; acc[7] = acc[7] * scale + ex * v1.w;
        m = mnew;
    }
    {   // self loop (src = dst = d)
        float a = g_als[d * NH + h] + aldh + alec[(size_t)(NE + d) * NH + h];
        a = (a > 0.f) ? a : 0.2f * a;
        float mnew = fmaxf(m, a);
        float scale = __expf(m - mnew);
        float ex = __expf(a - mnew);
        den = den * scale + ex;
        const float4* hp = (const float4*)&g_h[(size_t)d * HC + lane * 8];
        float4 v0 = hp[0], v1 = hp[1];
        acc[0] = acc[0] * scale + ex * v0.x; acc[1] = acc[1] * scale + ex * v0.y;
        acc[2] = acc[2] * scale + ex * v0.z; acc[3] = acc[3] * scale + ex * v0.w;
        acc[4] = acc[4] * scale + ex * v1.x; acc[5] = acc[5] * scale + ex * v1.y;
        acc[6] = acc[6] * scale + ex * v1.z; acc[7] = acc[7] * scale + ex * v1.w;
    }
    float inv = 1.f / (den + 1e-16f);
    int col = lane * 8;
    float o[8];
#pragma unroll
    for (int j = 0; j < 8; j++) {
        float v = acc[j] * inv + b[col + j];
        o[j] = fmaxf(v, 0.f);
    }
    size_t base = (size_t)d * HC + col;
    if (mode != 2) {
        // split output into fp16 planes for the next GEMM
        unsigned short hs[8], ls[8];
#pragma unroll
        for (int j = 0; j < 8; j++) split2(o[j], hs[j], ls[j]);
        uint4 uh, ul;
        uh.x = (uint32_t)hs[0] | ((uint32_t)hs[1] << 16);
        uh.y = (uint32_t)hs[2] | ((uint32_t)hs[3] << 16);
        uh.z = (uint32_t)hs[4] | ((uint32_t)hs[5] << 16);
        uh.w = (uint32_t)hs[6] | ((uint32_t)hs[7] << 16);
        ul.x = (uint32_t)ls[0] | ((uint32_t)ls[1] << 16);
        ul.y = (uint32_t)ls[2] | ((uint32_t)ls[3] << 16);
        ul.z = (uint32_t)ls[4] | ((uint32_t)ls[5] << 16);
        ul.w = (uint32_t)ls[6] | ((uint32_t)ls[7] << 16);
        *(uint4*)&g_ap_hi[base] = uh;
        *(uint4*)&g_ap_lo[base] = ul;
    }
    float na[8];
    if (mode == 0) {
#pragma unroll
        for (int j = 0; j < 8; j++) na[j] = o[j];
    } else {
        float4 a0 = *(float4*)&g_add[base], a1 = *(float4*)&g_add[base + 4];
        na[0] = a0.x + o[0]; na[1] = a0.y + o[1]; na[2] = a0.z + o[2]; na[3] = a0.w + o[3];
        na[4] = a1.x + o[4]; na[5] = a1.y + o[5]; na[6] = a1.z + o[6]; na[7] = a1.w + o[7];
    }
    *(float4*)&g_add[base]     = *(float4*)&na[0];
    *(float4*)&g_add[base + 4] = *(float4*)&na[4];

    if (mode == 2) {
        // fused SAGPool row dots: t = add.wrel, score = add.wroot + brel
        float t = 0.f, r = 0.f;
#pragma unroll
        for (int j = 0; j < 8; j++) {
            t += na[j] * wrel[col + j];
            r += na[j] * wroot[col + j];
        }
#pragma unroll
        for (int s = 16; s > 0; s >>= 1) {
            t += __shfl_xor_sync(0xFFFFFFFFu, t, s);
            r += __shfl_xor_sync(0xFFFFFFFFu, r, s);
        }
        if (lane == 0) { g_t[d] = t; g_score[d] = r + brel[0]; }
    }
}

// deterministic CSR gather (double accumulate)
__global__ void k_scoreagg() {
    int d = blockIdx.x * blockDim.x + threadIdx.x;
    if (d >= NN) return;
    double s = 0.0;
    int beg = g_rowstart[d], end = g_rowstart[d + 1];
    for (int i = beg; i < end; i++) s += (double)g_t[g_csrsrc[i]];
    g_score[d] += (float)s;
}

// ---------------- group boundaries (batch is sorted) --------------------------
__global__ void k_gstart(const int* __restrict__ batch) {
    int n = blockIdx.x * blockDim.x + threadIdx.x;
    if (n >= NN) return;
    int b = batch[n];
    int prev = (n == 0) ? -1 : batch[n - 1];
    for (int g = prev + 1; g <= b; g++) g_gstart[g] = n;
    if (n == NN - 1) {
        for (int g = b + 1; g <= NGRP; g++) g_gstart[g] = NN;
    }
}

// ---------------- per-group bitonic sort (descending score, tie: asc index) --
#define SORTP 1024
__global__ void k_sort() {
    __shared__ float sk[SORTP];
    __shared__ int   sv[SORTP];
    int g = blockIdx.x;
    int start = g_gstart[g], end = g_gstart[g + 1];
    int sz = end - start;
    if (sz > SORTP) sz = SORTP;
    for (int i = threadIdx.x; i < SORTP; i += blockDim.x) {
        if (i < sz) { sk[i] = g_score[start + i]; sv[i] = start + i; }
        else        { sk[i] = -FLT_MAX; sv[i] = 0x7FFFFFFF; }
    }
    __syncthreads();
    for (int k = 2; k <= SORTP; k <<= 1) {
        for (int j = k >> 1; j > 0; j >>= 1) {
            for (int i = threadIdx.x; i < SORTP; i += blockDim.x) {
                int ixj = i ^ j;
                if (ixj > i) {
                    float ki = sk[i], kj = sk[ixj];
                    int vi = sv[i], vj = sv[ixj];
                    bool before = (kj > ki) || (kj == ki && vj < vi);
                    bool dir = ((i & k) == 0);
                    if (before == dir) {
                        sk[i] = kj; sk[ixj] = ki;
                        sv[i] = vj; sv[ixj] = vi;
                    }
                }
            }
            __syncthreads();
        }
    }
    for (int i = threadIdx.x; i < sz; i += blockDim.x) g_perm[start + i] = sv[i];
}

// ---------------- final: gate + 256->10 GEMV + sigmoid ------------------------
__global__ void k_final(const float* __restrict__ wl, const float* __restrict__ bl,
                        float* __restrict__ out) {
    __shared__ float swl[HC * NOUT];
    for (int i = threadIdx.x; i < HC * NOUT; i += blockDim.x) swl[i] = wl[i];
    __syncthreads();
    int pos = blockIdx.x * 8 + (threadIdx.x >> 5);
    int lane = threadIdx.x & 31;
    if (pos >= NN) return;
    int p = g_perm[pos];
    float ts = tanhf(g_score[p]);
    float acc[NOUT];
#pragma unroll
    for (int o = 0; o < NOUT; o++) acc[o] = 0.f;
    size_t base = (size_t)p * HC + lane * 8;
#pragma unroll
    for (int jj = 0; jj < 8; jj++) {
        float v = g_add[base + jj] * ts;
        const float* wrow = &swl[(lane * 8 + jj) * NOUT];
#pragma unroll
        for (int o = 0; o < NOUT; o++) acc[o] += v * wrow[o];
    }
#pragma unroll
    for (int s = 16; s > 0; s >>= 1)
#pragma unroll
        for (int o = 0; o < NOUT; o++) acc[o] += __shfl_xor_sync(0xFFFFFFFFu, acc[o], s);
    if (lane == 0) {
#pragma unroll
        for (int o = 0; o < NOUT; o++)
            out[(size_t)pos * NOUT + o] = 1.f / (1.f + expf(-(acc[o] + bl[o])));
    }
}

// ---------------- launch ------------------------------------------------------
extern "C" void kernel_launch(void* const* d_in, const int* in_sizes, int n_in,
                              void* d_out, int out_size) {
    const float* x     = (const float*)d_in[0];
    const int*   eidx  = (const int*)d_in[1];
    const int*   batch = (const int*)d_in[2];
    const float* ea    = (const float*)d_in[3];
    const float* W[3]  = {(const float*)d_in[4],  (const float*)d_in[10], (const float*)d_in[16]};
    const float* AS[3] = {(const float*)d_in[5],  (const float*)d_in[11], (const float*)d_in[17]};
    const float* AD[3] = {(const float*)d_in[6],  (const float*)d_in[12], (const float*)d_in[18]};
    const float* WE[3] = {(const float*)d_in[7],  (const float*)d_in[13], (const float*)d_in[19]};
    const float* AE[3] = {(const float*)d_in[8],  (const float*)d_in[14], (const float*)d_in[20]};
    const float* B[3]  = {(const float*)d_in[9],  (const float*)d_in[15], (const float*)d_in[21]};
    const float* wrel  = (const float*)d_in[22];
    const float* brel  = (const float*)d_in[23];
    const float* wroot = (const float*)d_in[24];
    const float* wl    = (const float*)d_in[25];
    const float* bl    = (const float*)d_in[26];

    const int* src = eidx;
    const int* dst = eidx + NE;

    static cudaStream_t s2 = nullptr;
    static cudaEvent_t evA = nullptr, evB = nullptr;
    if (!s2) {
        cudaStreamCreateWithFlags(&s2, cudaStreamNonBlocking);
        cudaEventCreateWithFlags(&evA, cudaEventDisableTiming);
        cudaEventCreateWithFlags(&evB, cudaEventDisableTiming);
        cudaFuncSetAttribute(k_gemm, cudaFuncAttributeMaxDynamicSharedMemorySize, SMEM_BYTES);
    }

    const int T = 256;

    // ---- fork: CSR/logit prologue chain on s2 ----
    cudaEventRecord(evA, 0);
    cudaStreamWaitEvent(s2, evA, 0);
    k_weeff3<<<3, 64, 0, s2>>>(WE[0], AE[0], WE[1], AE[1], WE[2], AE[2]);
    k_gstart<<<(NN + T - 1) / T, T, 0, s2>>>(batch);
    k_init0<<<(NN + T - 1) / T, T, 0, s2>>>();
    k_deg<<<(NE + T - 1) / T, T, 0, s2>>>(dst);
    k_scan1<<<SCANB, 1024, 0, s2>>>();
    k_scan2<<<1, 32, 0, s2>>>();
    k_scan3<<<SCANB, 1024, 0, s2>>>();
    k_fill<<<(NE + T - 1) / T, T, 0, s2>>>(src, dst);
    k_meacsr<<<(NN + 15) / 16, T, 0, s2>>>(ea);
    k_ale3<<<(NEF + T - 1) / T, T, 0, s2>>>(ea);
    cudaEventRecord(evB, s2);

    // primary stream: weight/input prep + layer-0 GEMM (independent of CSR)
    k_splitx<<<(NN * FIN / 2 + T - 1) / T, T>>>(x);
    k_prepw<<<(FIN * HC + 2 * HC * HC + T - 1) / T, T>>>(W[0], W[1], W[2]);

    for (int l = 0; l < 3; l++) {
        int K = (l == 0) ? FIN : HC;
        k_zals<<<(NN * NH + T - 1) / T, T>>>();
        k_gemm<<<dim3(HC / 128, (NN + 127) / 128), T, SMEM_BYTES>>>(K, AS[l], AD[l], l);
        if (l == 0) cudaStreamWaitEvent(0, evB, 0);  // join: gather needs CSR + ale3
        k_gather<<<(NN + 7) / 8, T>>>(B[l], (l == 0) ? 0 : (l == 2) ? 2 : 1, l,
                                      wrel, wroot, brel);
    }

    // SAGPool score (deterministic CSR aggregation; t/score already computed)
    k_scoreagg<<<(NN + T - 1) / T, T>>>();

    // per-graph sort + final head
    k_sort<<<NGRP, 512>>>();
    k_final<<<(NN + 7) / 8, T>>>(wl, bl, (float*)d_out);
}